// round 5
// baseline (speedup 1.0000x reference)
#include <cuda_runtime.h>
#include <cuda_bf16.h>
#include <cstdint>

// Problem constants
#define NN   512
#define BB   128
#define TT   1000
#define INPD 6

#define CLSZ    8     // cluster size (CTAs)
#define NCLUST  16    // 128 batches / 8 per cluster
#define ROWS    64    // N rows per CTA
#define THREADS 256
#define WPAD    516   // padded row stride for W in smem (conflict-free LDS.128)

// smem layout (floats)
#define OFF_W      0
#define OFF_SBUF   (ROWS * WPAD)                    // 33024
#define OFF_SCR    (OFF_SBUF + 2 * NN * 8)          // 41216
#define OFF_UIN    (OFF_SCR + 1536)                 // 42752
#define OFF_WINP   (OFF_UIN + 64)                   // 42816
#define OFF_WOUT   (OFF_WINP + 384)                 // 43200
#define SMEM_FLOATS (OFF_WOUT + 512)                // 43712
#define SMEM_BYTES  (SMEM_FLOATS * 4)               // 174848

typedef unsigned long long u64;

// global exchange buffer: [2][NCLUST][512][8] floats
__device__ float g_sx[2 * NCLUST * NN * 8];

__device__ __forceinline__ u64 pk2(float lo, float hi) {
    u64 r; asm("mov.b64 %0,{%1,%2};" : "=l"(r) : "f"(lo), "f"(hi)); return r;
}
__device__ __forceinline__ u64 f2fma(u64 a, u64 b, u64 c) {
    u64 d; asm("fma.rn.f32x2 %0,%1,%2,%3;" : "=l"(d) : "l"(a), "l"(b), "l"(c)); return d;
}
__device__ __forceinline__ u64 f2add(u64 a, u64 b) {
    u64 d; asm("add.rn.f32x2 %0,%1,%2;" : "=l"(d) : "l"(a), "l"(b)); return d;
}
__device__ __forceinline__ float2 up2(u64 a) {
    float2 f; asm("mov.b64 {%0,%1},%2;" : "=f"(f.x), "=f"(f.y) : "l"(a)); return f;
}
__device__ __forceinline__ void cluster_arrive() {
    asm volatile("barrier.cluster.arrive.aligned;" ::: "memory");
}
__device__ __forceinline__ void cluster_wait() {
    asm volatile("barrier.cluster.wait.aligned;" ::: "memory");
}

__global__ void __cluster_dims__(CLSZ, 1, 1) __launch_bounds__(THREADS, 1)
rnn_kernel(const float* __restrict__ u, const float* __restrict__ rnoise,
           const float* __restrict__ inoise, const float* __restrict__ Wr,
           const float* __restrict__ Wi, const float* __restrict__ Wo,
           const float* __restrict__ y0, float* __restrict__ states,
           float* __restrict__ outputs)
{
    extern __shared__ float sm[];
    float* smW   = sm + OFF_W;      // [64][516]
    float* sbuf  = sm + OFF_SBUF;   // [2][512][8]
    u64*   scr   = (u64*)(sm + OFF_SCR);  // [3][2][32][4] u64
    float* uin   = sm + OFF_UIN;    // [6][8]
    float* winp  = sm + OFF_WINP;   // [64][6]
    float* wout  = sm + OFF_WOUT;   // [512]

    const int tid  = threadIdx.x;
    const int wid  = tid >> 5;
    const int lane = tid & 31;
    const int kc   = wid >> 1;      // K-chunk 0..3
    const int rg   = wid & 1;       // row-group 0/1
    const int rl   = rg * 32 + lane;  // local row 0..63

    const int rank  = blockIdx.x & (CLSZ - 1);
    const int cl    = blockIdx.x >> 3;
    const int rbase = rank * ROWS;   // global row base
    const int bbase = cl * 8;        // global batch base

    const float ALPHA_F = (float)(1.0 / 10.0);
    const float OMA     = 1.0f - ALPHA_F;

    // ---- setup: load W_rec slice (row-major, padded stride 516) ----
    for (int idx = tid * 4; idx < ROWS * NN; idx += THREADS * 4) {
        int r = idx >> 9, k = idx & (NN - 1);
        *(float4*)(smW + r * WPAD + k) = *(const float4*)(Wr + (size_t)(rbase + r) * NN + k);
    }
    for (int idx = tid; idx < ROWS * INPD; idx += THREADS)
        winp[idx] = Wi[(size_t)rbase * INPD + idx];
    for (int idx = tid; idx < NN; idx += THREADS)
        wout[idx] = Wo[idx];
    // initial state into sbuf[0], broadcast across the 8 batch slots
    for (int k = tid; k < NN; k += THREADS) {
        float v = y0[k];
        #pragma unroll
        for (int b = 0; b < 8; b++) sbuf[k * 8 + b] = v;
    }
    // states[:, 0, :] for this CTA's (batches x rows) tile
    for (int idx = tid; idx < 8 * ROWS; idx += THREADS) {
        int b = idx >> 6, r = idx & (ROWS - 1);
        __stcs(states + (size_t)(bbase + b) * TT * NN + rbase + r, y0[rbase + r]);
    }
    __syncthreads();

    // ---- main recurrence: t = 0 .. T-2 ----
    for (int t = 0; t < TT - 1; ++t) {
        const int pc = t & 1, pn = pc ^ 1;
        const float* sb = sbuf + pc * (NN * 8);

        // prefetch this step's rec_noise for our rows (epilogue warps only)
        float rnv[8];
        if (kc == 0) {
            const float* rp = rnoise + (size_t)t * NN + rbase + rl;
            #pragma unroll
            for (int b = 0; b < 8; b++)
                rnv[b] = __ldcs(rp + (size_t)(bbase + b) * TT * NN);
        }
        // prefetch (u + inp_noise) for this step into smem
        if (wid == 2) {
            for (int idx = lane; idx < 48; idx += 32) {
                int b = idx & 7, j = idx >> 3;
                size_t gi = (size_t)(bbase + b) * TT * INPD + (size_t)t * INPD + j;
                uin[j * 8 + b] = u[gi] + inoise[gi];
            }
        }

        // ---- K-loop: pre[rl][0..7] partials over k-chunk [kc*128, kc*128+128) ----
        u64 acc0 = 0, acc1 = 0, acc2 = 0, acc3 = 0;
        {
            const float* wrow = smW + rl * WPAD;
            const int k0 = kc * 128;
            #pragma unroll 8
            for (int k = k0; k < k0 + 128; k += 4) {
                float4 w4 = *(const float4*)(wrow + k);
                #pragma unroll
                for (int i = 0; i < 4; i++) {
                    const float wv = (i == 0) ? w4.x : (i == 1) ? w4.y : (i == 2) ? w4.z : w4.w;
                    u64 wd = pk2(wv, wv);
                    ulonglong2 sA = *(const ulonglong2*)(sb + (k + i) * 8);
                    ulonglong2 sB = *(const ulonglong2*)(sb + (k + i) * 8 + 4);
                    acc0 = f2fma(wd, sA.x, acc0);
                    acc1 = f2fma(wd, sA.y, acc1);
                    acc2 = f2fma(wd, sB.x, acc2);
                    acc3 = f2fma(wd, sB.y, acc3);
                }
            }
        }

        // stash partials for K-chunks 1..3
        if (kc > 0) {
            u64* sc = scr + (((kc - 1) * 2 + rg) * 32 + lane) * 4;
            ulonglong2 a; a.x = acc0; a.y = acc1;
            ulonglong2 b2; b2.x = acc2; b2.y = acc3;
            *(ulonglong2*)sc = a;
            *(ulonglong2*)(sc + 2) = b2;
        }
        __syncthreads();

        if (kc == 0) {
            // reduce 4 K-chunk partials
            #pragma unroll
            for (int c = 0; c < 3; c++) {
                const u64* sc = scr + ((c * 2 + rg) * 32 + lane) * 4;
                ulonglong2 qa = *(const ulonglong2*)sc;
                ulonglong2 qb = *(const ulonglong2*)(sc + 2);
                acc0 = f2add(acc0, qa.x); acc1 = f2add(acc1, qa.y);
                acc2 = f2add(acc2, qb.x); acc3 = f2add(acc3, qb.y);
            }
            float pre[8];
            { float2 q = up2(acc0); pre[0] = q.x; pre[1] = q.y; }
            { float2 q = up2(acc1); pre[2] = q.x; pre[3] = q.y; }
            { float2 q = up2(acc2); pre[4] = q.x; pre[5] = q.y; }
            { float2 q = up2(acc3); pre[6] = q.x; pre[7] = q.y; }

            // + (u + inp_noise) @ W_inp^T
            #pragma unroll
            for (int j = 0; j < INPD; j++) {
                float wij = winp[rl * INPD + j];
                const float* up = uin + j * 8;
                #pragma unroll
                for (int b = 0; b < 8; b++) pre[b] += wij * up[b];
            }

            // s_new = (1-a)*s + a*(relu(pre) + rn)
            const float4 so0 = *(const float4*)(sb + (rbase + rl) * 8);
            const float4 so1 = *(const float4*)(sb + (rbase + rl) * 8 + 4);
            const float sold[8] = {so0.x, so0.y, so0.z, so0.w, so1.x, so1.y, so1.z, so1.w};
            float sn[8];
            #pragma unroll
            for (int b = 0; b < 8; b++) {
                float v = fmaxf(pre[b], 0.0f) + rnv[b];
                sn[b] = OMA * sold[b] + ALPHA_F * v;
            }

            // publish slice to the cluster exchange buffer (double-buffered)
            float* dg = g_sx + ((size_t)pn * NCLUST + cl) * (NN * 8) + (rbase + rl) * 8;
            *(float4*)dg       = make_float4(sn[0], sn[1], sn[2], sn[3]);
            *(float4*)(dg + 4) = make_float4(sn[4], sn[5], sn[6], sn[7]);

            // states[:, t+1, rows]
            #pragma unroll
            for (int b = 0; b < 8; b++)
                __stcs(states + (size_t)(bbase + b) * TT * NN + (size_t)(t + 1) * NN + rbase + rl, sn[b]);
        } else if (wid == 7) {
            // outputs[bbase+rank, t] = dot(s_t, W_out)
            float v = 0.0f;
            #pragma unroll
            for (int i = 0; i < 16; i++) {
                int k = lane + 32 * i;
                v += sb[k * 8 + rank] * wout[k];
            }
            #pragma unroll
            for (int off = 16; off; off >>= 1) v += __shfl_xor_sync(0xffffffffu, v, off);
            if (lane == 0) outputs[(size_t)(bbase + rank) * TT + t] = v;
        }

        // release our slice, acquire everyone's
        cluster_arrive();
        cluster_wait();

        // refill full next-state into local smem (L1 bypass: buffer alternates)
        {
            const float4* src = (const float4*)(g_sx + ((size_t)pn * NCLUST + cl) * (NN * 8));
            float4* dst = (float4*)(sbuf + pn * (NN * 8));
            #pragma unroll
            for (int i = 0; i < 4; i++)
                dst[tid + i * THREADS] = __ldcg(src + tid + i * THREADS);
        }
        __syncthreads();
    }

    // final output: outputs[:, T-1] from s_{T-1}
    if (wid == 7) {
        const float* sbf = sbuf + ((TT - 1) & 1) * (NN * 8);
        float v = 0.0f;
        #pragma unroll
        for (int i = 0; i < 16; i++) {
            int k = lane + 32 * i;
            v += sbf[k * 8 + rank] * wout[k];
        }
        #pragma unroll
        for (int off = 16; off; off >>= 1) v += __shfl_xor_sync(0xffffffffu, v, off);
        if (lane == 0) outputs[(size_t)(bbase + rank) * TT + (TT - 1)] = v;
    }
}

extern "C" void kernel_launch(void* const* d_in, const int* in_sizes, int n_in,
                              void* d_out, int out_size)
{
    const float* u      = (const float*)d_in[0];
    const float* rnoise = (const float*)d_in[1];
    const float* inoise = (const float*)d_in[2];
    const float* Wr     = (const float*)d_in[3];
    const float* Wi     = (const float*)d_in[4];
    const float* Wo     = (const float*)d_in[5];
    const float* y0     = (const float*)d_in[6];

    float* states  = (float*)d_out;
    float* outputs = states + (size_t)BB * TT * NN;

    cudaFuncSetAttribute(rnn_kernel, cudaFuncAttributeMaxDynamicSharedMemorySize, SMEM_BYTES);
    rnn_kernel<<<NCLUST * CLSZ, THREADS, SMEM_BYTES>>>(u, rnoise, inoise, Wr, Wi, Wo, y0,
                                                       states, outputs);
}